// round 14
// baseline (speedup 1.0000x reference)
#include <cuda_runtime.h>
#include <cuda_bf16.h>
#include <math.h>
#include <cstdint>

// Shapes (fixed)
//   x: (4,256,64,64) f32 | conv_offset_w: (27,256,3,3) | conv_offset_b: (27,)
//   dcn_weight: (256,256,3,3) | out: (4,256,64,64) f32
//
// Pipeline (all tensor-core):
//   K0  transpose x -> g_xT[n][py][px][c] (67x67 zero-padded, channel-last)
//   K2a permute dcn_weight    -> g_wB[o][k']       tf32, k 8-group permuted
//   K2b permute conv_offset_w -> g_wOffHi/Lo[32][k'] split-tf32
//   K3  offset implicit GEMM  -> g_om   (NCHW window reads, L1-hot)
//   K4  FUSED sample+GEMM, SPLIT-K x2, BM=64, 2 CTAs/SM, xT gather with
//       lanes-over-channels (1 wavefront per warp-LDG) -> g_part[2]
//   K5  add partials -> out

#define NN 4
#define CC 256
#define HH 64
#define WW 64
#define OC 256
#define KDIM 2304
#define MDIM 16384
#define NTILES 72
#define PARTSZ ((size_t)MDIM * OC)

#define PXW   67
#define ROWE  (PXW * 256)
#define PLANE (PXW * PXW * 256)

__device__ __align__(128) float g_om[NN * 27 * HH * WW];
__device__ __align__(128) float g_wB[OC * KDIM];
__device__ __align__(128) float g_wOffHi[32 * KDIM];
__device__ __align__(128) float g_wOffLo[32 * KDIM];
__device__ __align__(128) float g_part[2 * PARTSZ];          // 33.5 MB
__device__ __align__(128) float g_xT[(size_t)NN * PLANE];    // 18.4 MB

__device__ __forceinline__ float to_tf32(float v) {
    uint32_t u;
    asm("cvt.rna.tf32.f32 %0, %1;" : "=r"(u) : "f"(v));
    return __uint_as_float(u);
}
__device__ __forceinline__ uint32_t smem_u32(const void* p) {
    uint32_t a;
    asm("{ .reg .u64 t; cvta.to.shared.u64 t, %1; cvt.u32.u64 %0, t; }"
        : "=r"(a) : "l"(p));
    return a;
}
__device__ __forceinline__ void cp_async16(uint32_t d, const void* s) {
    asm volatile("cp.async.cg.shared.global [%0], [%1], 16;"
                 :: "r"(d), "l"(s) : "memory");
}
__device__ __forceinline__ void sts32(uint32_t a, float v) {
    asm volatile("st.shared.b32 [%0], %1;" :: "r"(a), "r"(__float_as_uint(v)) : "memory");
}

#define MMA_TF32(c_, a_, b_)                                                  \
    asm volatile(                                                             \
        "mma.sync.aligned.m16n8k8.row.col.f32.tf32.tf32.f32 "                 \
        "{%0,%1,%2,%3}, {%4,%5,%6,%7}, {%8,%9}, {%0,%1,%2,%3};"               \
        : "+f"((c_)[0]), "+f"((c_)[1]), "+f"((c_)[2]), "+f"((c_)[3])          \
        : "r"((a_)[0]), "r"((a_)[1]), "r"((a_)[2]), "r"((a_)[3]),             \
          "r"((b_)[0]), "r"((b_)[1]))

// ---------------------------------------------------------------------------
// K0: transpose x (NCHW) -> g_xT (padded, channel-last)
// ---------------------------------------------------------------------------
__global__ __launch_bounds__(256) void transpose_x_kernel(const float* __restrict__ x)
{
    int py = blockIdx.x;
    int n  = blockIdx.y;
    int t  = threadIdx.x;
    float* dst = g_xT + (size_t)(n * PXW + py) * ROWE;

    if (py < 1 || py > 64) {
        for (int i = t; i < ROWE; i += 256) dst[i] = 0.f;
        return;
    }
    __shared__ float sx[128][65];
    for (int c0 = 0; c0 < 256; c0 += 128) {
        for (int i = t; i < 128 * 64; i += 256) {
            int ch = i >> 6, xx = i & 63;
            sx[ch][xx] = x[(((size_t)(n * 256 + c0 + ch)) * 64 + (py - 1)) * 64 + xx];
        }
        __syncthreads();
        for (int i = t; i < PXW * 128; i += 256) {
            int px_ = i >> 7, c = i & 127;
            dst[px_ * 256 + c0 + c] = (px_ >= 1 && px_ <= 64) ? sx[c][px_ - 1] : 0.f;
        }
        __syncthreads();
    }
}

// ---------------------------------------------------------------------------
// K2a: permute dcn_weight (o,c,kk) -> g_wB[o][k'], tf32-rounded, k-permuted
// ---------------------------------------------------------------------------
__global__ __launch_bounds__(256) void permute_w_kernel(const float* __restrict__ dw)
{
    int o = blockIdx.x;
    int c = threadIdx.x;
    int cp = (c & 0xF8) | ((c & 3) << 1) | ((c >> 2) & 1);
    const float* src = dw + (size_t)(o * CC + c) * 9;
    float* dst = g_wB + (size_t)o * KDIM + cp;
#pragma unroll
    for (int kk = 0; kk < 9; kk++)
        dst[kk * 256] = to_tf32(src[kk]);
}

// ---------------------------------------------------------------------------
// K2b: permute conv_offset_w -> g_wOffHi/Lo[32][k'] (split-tf32)
// ---------------------------------------------------------------------------
__global__ __launch_bounds__(256) void permute_woff_kernel(const float* __restrict__ wo)
{
    int o = blockIdx.x;
    int c = threadIdx.x;
    int cp = (c & 0xF8) | ((c & 3) << 1) | ((c >> 2) & 1);
    float* dh = g_wOffHi + (size_t)o * KDIM + cp;
    float* dl = g_wOffLo + (size_t)o * KDIM + cp;
    if (o < 27) {
        const float* src = wo + (size_t)(o * CC + c) * 9;
#pragma unroll
        for (int kk = 0; kk < 9; kk++) {
            float v = src[kk];
            float h = to_tf32(v);
            dh[kk * 256] = h;
            dl[kk * 256] = to_tf32(v - h);
        }
    } else {
#pragma unroll
        for (int kk = 0; kk < 9; kk++) { dh[kk * 256] = 0.f; dl[kk * 256] = 0.f; }
    }
}

// ---------------------------------------------------------------------------
// K3: offset conv, split-tf32 implicit GEMM, NCHW window gather (unchanged,
// measured ~101 us).
// ---------------------------------------------------------------------------
#define OSM_A 0
#define OSM_B 65536
#define OFF_SMEM 98304

__global__ __launch_bounds__(256, 1) void offset_gemm_kernel(
    const float* __restrict__ x, const float* __restrict__ bias)
{
    extern __shared__ __align__(128) char smem[];
    const uint32_t sbase = smem_u32(smem);
    const int tid = threadIdx.x;
    const int m0 = blockIdx.x * 128;
    const int nimg = m0 >> 12;
    const int y0 = (m0 & 4095) >> 6;

    const int ldrow = tid >> 3;
    const int ldcol = tid & 7;
    const int swzb  = ldcol ^ (ldrow & 7);
    const char* gBh = (const char*)(g_wOffHi + (size_t)ldrow * KDIM) + ldcol * 16;
    const char* gBl = (const char*)(g_wOffLo + (size_t)ldrow * KDIM) + ldcol * 16;
    const uint32_t dBh = sbase + OSM_B + ldrow * 128 + swzb * 16;

#define LOAD_OB(tt_) do {                                                     \
    uint32_t so_ = ((tt_) & 3) * 8192;                                        \
    size_t   ko_ = (size_t)(tt_) * 128;                                       \
    cp_async16(dBh + so_, gBh + ko_);                                         \
    cp_async16(dBh + so_ + 4096, gBl + ko_);                                  \
} while (0)

    LOAD_OB(0); asm volatile("cp.async.commit_group;" ::: "memory");
    LOAD_OB(1); asm volatile("cp.async.commit_group;" ::: "memory");
    LOAD_OB(2); asm volatile("cp.async.commit_group;" ::: "memory");

    const int mloc = tid & 127;
    const int half = tid >> 7;
    const int lane = tid & 31, warp = tid >> 5;
    const int g  = lane >> 2, tg = lane & 3;
    const int wm = warp * 16;

    const float* xn = x + (size_t)nimg * CC * 4096;

    float c[4][4];
#pragma unroll
    for (int i = 0; i < 4; i++)
#pragma unroll
        for (int r = 0; r < 4; r++) c[i][r] = 0.f;

    int soff = 0;
    bool valid = false;
    float R0[16], R1[16];

    auto gather16 = [&](float* R, int tt) {
        if ((tt & 7) == 0) {
            int kk = tt >> 3;
            int yy = y0 + (mloc >> 6) + kk / 3 - 1;
            int xx = (mloc & 63) + kk % 3 - 1;
            valid = ((unsigned)yy < 64u) && ((unsigned)xx < 64u);
            soff = yy * 64 + xx;
        }
        const float* xp = xn + (size_t)((tt & 7) * 32) * 4096;
#pragma unroll
        for (int i = 0; i < 8; i++) {
            int ct = half * 16 + (i >> 2) * 8 + (i & 3);
            R[i * 2]     = valid ? __ldg(xp + (size_t)ct * 4096 + soff) : 0.f;
            R[i * 2 + 1] = valid ? __ldg(xp + (size_t)(ct + 4) * 4096 + soff) : 0.f;
        }
    };
    auto sts16 = [&](const float* R, int tt) {
        const uint32_t Awh = sbase + OSM_A + (tt & 1) * 32768 + mloc * 128;
#pragma unroll
        for (int i = 0; i < 8; i++) {
            int q = i & 3;
            int ct = half * 16 + (i >> 2) * 8 + q;
            float v0 = R[i * 2], v1 = R[i * 2 + 1];
            float h0 = to_tf32(v0), l0 = to_tf32(v0 - h0);
            float h1 = to_tf32(v1), l1 = to_tf32(v1 - h1);
            int cp = (ct & 0x18) | (q << 1);
            uint32_t off = ((((uint32_t)cp >> 2) ^ (mloc & 7)) << 4) + ((cp & 3) << 2);
            asm volatile("st.shared.v2.b32 [%0], {%1,%2};"
                         :: "r"(Awh + off),
                            "r"(__float_as_uint(h0)), "r"(__float_as_uint(h1)) : "memory");
            asm volatile("st.shared.v2.b32 [%0], {%1,%2};"
                         :: "r"(Awh + 16384 + off),
                            "r"(__float_as_uint(l0)), "r"(__float_as_uint(l1)) : "memory");
        }
    };
    auto mma_tile = [&](int tt) {
        const uint32_t As = sbase + OSM_A + (tt & 1) * 32768;
        const uint32_t Bs = sbase + OSM_B + (tt & 3) * 8192;
#pragma unroll
        for (int ks = 0; ks < 4; ks++) {
            const int ch = ks * 2 + (tg >> 1);
            const int hb = (tg & 1) << 3;
            uint32_t ah[4], al[4];
            {
                int r1 = wm + g, r2 = r1 + 8;
                uint32_t ad1 = As + r1 * 128 + ((ch ^ (r1 & 7)) << 4) + hb;
                uint32_t ad2 = As + r2 * 128 + ((ch ^ (r2 & 7)) << 4) + hb;
                asm volatile("ld.shared.v2.b32 {%0,%1}, [%2];"
                             : "=r"(ah[0]), "=r"(ah[2]) : "r"(ad1));
                asm volatile("ld.shared.v2.b32 {%0,%1}, [%2];"
                             : "=r"(ah[1]), "=r"(ah[3]) : "r"(ad2));
                asm volatile("ld.shared.v2.b32 {%0,%1}, [%2];"
                             : "=r"(al[0]), "=r"(al[2]) : "r"(ad1 + 16384));
                asm volatile("ld.shared.v2.b32 {%0,%1}, [%2];"
                             : "=r"(al[1]), "=r"(al[3]) : "r"(ad2 + 16384));
            }
#pragma unroll
            for (int nt = 0; nt < 4; nt++) {
                int rr = nt * 8 + g;
                uint32_t bd = Bs + rr * 128 + ((ch ^ (rr & 7)) << 4) + hb;
                uint32_t bh[2], bl[2];
                asm volatile("ld.shared.v2.b32 {%0,%1}, [%2];"
                             : "=r"(bh[0]), "=r"(bh[1]) : "r"(bd));
                asm volatile("ld.shared.v2.b32 {%0,%1}, [%2];"
                             : "=r"(bl[0]), "=r"(bl[1]) : "r"(bd + 4096));
                MMA_TF32(c[nt], ah, bh);
                MMA_TF32(c[nt], ah, bl);
                MMA_TF32(c[nt], al, bh);
            }
        }
    };

    gather16(R0, 0);

#pragma unroll 1
    for (int t = 0; t < NTILES; t += 2) {
        sts16(R0, t);
        gather16(R1, t + 1);
        asm volatile("cp.async.wait_group 2;" ::: "memory");
        __syncthreads();
        if (t + 3 < NTILES) LOAD_OB(t + 3);
        asm volatile("cp.async.commit_group;" ::: "memory");
        mma_tile(t);

        sts16(R1, t + 1);
        if (t + 2 < NTILES) gather16(R0, t + 2);
        asm volatile("cp.async.wait_group 2;" ::: "memory");
        __syncthreads();
        if (t + 4 < NTILES) LOAD_OB(t + 4);
        asm volatile("cp.async.commit_group;" ::: "memory");
        mma_tile(t + 1);
    }

    float* ob = g_om + (size_t)nimg * 27 * 4096 + (m0 & 4095);
    int lm = wm + g;
#pragma unroll
    for (int nt = 0; nt < 4; nt++) {
        int oc0 = nt * 8 + tg * 2;
        if (oc0 < 27) {
            float bb = bias[oc0];
            ob[(size_t)oc0 * 4096 + lm]     = c[nt][0] + bb;
            ob[(size_t)oc0 * 4096 + lm + 8] = c[nt][2] + bb;
        }
        if (oc0 + 1 < 27) {
            float bb = bias[oc0 + 1];
            ob[(size_t)(oc0 + 1) * 4096 + lm]     = c[nt][1] + bb;
            ob[(size_t)(oc0 + 1) * 4096 + lm + 8] = c[nt][3] + bb;
        }
    }
}

// ---------------------------------------------------------------------------
// K4: FUSED sample+GEMM, SPLIT-K x2, BM=64, 2 CTAs/SM, xT gather.
// grid=512 (mblk = bid>>1, kb = bid&1; kb handles tiles [kb*36, kb*36+36)).
// Gather: warp w covers pixels w*8..w*8+7; lanes = 32 channels -> each tap
// load is 128B contiguous (1 wavefront). Tap metadata (base addr + 4 folded
// weights per (pixel,kk)) precomputed in smem; weight reads are warp-uniform.
// smem: A 2x8KB @0 | B 2x32KB @16384 | sbse @81920 | swt @84224  (93440 B)
// ---------------------------------------------------------------------------
#define FSM_A  0
#define FSM_B  16384
#define FSM_SB 81920
#define FSM_SW 84224
#define FUSED_SMEM 93440

__global__ __launch_bounds__(256, 2) void fused_gemm_kernel()
{
    extern __shared__ __align__(128) char smem[];
    const uint32_t sb = smem_u32(smem);
    const int tid = threadIdx.x;
    const int bid = blockIdx.x;
    const int kb   = bid & 1;
    const int m0   = (bid >> 1) * 64;
    const int nimg = m0 >> 12;
    const int yrow = (m0 & 4095) >> 6;
    const int NT0 = kb * 36, NT1 = NT0 + 36;

    int*    sbse = (int*)(smem + FSM_SB);     // [576]
    float4* swt  = (float4*)(smem + FSM_SW);  // [576]

    // ---- B cp.async: 2048 chunks/stage, 8 per thread ----
    const int ldrow = tid >> 3;
    const int ldcol = tid & 7;
    const int swzb  = ldcol ^ (ldrow & 7);
    const char* gB0 = (const char*)(g_wB + (size_t)ldrow * KDIM) + ldcol * 16;
    const uint32_t dB0 = sb + FSM_B + ldrow * 128 + swzb * 16;

#define LOAD_B(tt_) do {                                                      \
    uint32_t so_ = ((tt_) & 1) * 32768;                                       \
    size_t   ko_ = (size_t)(tt_) * 128;                                       \
    _Pragma("unroll")                                                         \
    for (int i_ = 0; i_ < 8; i_++)                                            \
        cp_async16(dB0 + so_ + i_ * 4096,                                     \
                   gB0 + ko_ + (size_t)i_ * 32 * KDIM * 4);                   \
} while (0)

    LOAD_B(NT0);
    asm volatile("cp.async.commit_group;" ::: "memory");

    // ---- tap metadata: 64 pixels x 9 kk (overlaps with B stage-0 load) ----
    for (int idx = tid; idx < 576; idx += 256) {
        int p = idx / 9, kk = idx - p * 9;
        const float* omn = g_om + (size_t)nimg * 27 * 4096 + yrow * 64 + p;
        float oy = omn[(size_t)(2 * kk) * 4096];
        float ox = omn[(size_t)(2 * kk + 1) * 4096];
        float mv = omn[(size_t)(18 + kk) * 4096];
        float m  = 1.f / (1.f + __expf(-mv));

        float py = (float)(yrow + kk / 3) + oy;      // padded coords
        float px = (float)(p + kk % 3) + ox;
        py = fminf(fmaxf(py, 0.f), 65.f);
        px = fminf(fmaxf(px, 0.f), 65.f);
        float fy = floorf(py), fx = floorf(px);
        int y1 = (int)fy, x1 = (int)fx;
        float ly = py - fy, lx = px - fx;
        float hy = 1.f - ly, hx = 1.f - lx;

        sbse[idx] = (y1 * PXW + x1) * 256;
        float4 w4;
        w4.x = hy * hx * m; w4.y = hy * lx * m;
        w4.z = ly * hx * m; w4.w = ly * lx * m;
        swt[idx] = w4;
    }
    __syncthreads();   // metadata visible

    const int lane = tid & 31, warp = tid >> 5;
    const int g  = lane >> 2, tg = lane & 3;
    const int wm = (warp >> 2) * 32;
    const int wn = (warp & 3) * 64;
    const int lpos = (lane & 0x18) | ((lane & 3) << 1) | ((lane >> 2) & 1);
    const uint32_t lswz = (((uint32_t)lpos >> 2) << 4) + (((uint32_t)lpos & 3) << 2);
    const float* xTl = g_xT + (size_t)nimg * PLANE + lane;

    float c[2][8][4];
#pragma unroll
    for (int i = 0; i < 2; i++)
#pragma unroll
        for (int j = 0; j < 8; j++)
#pragma unroll
            for (int r = 0; r < 4; r++) c[i][j][r] = 0.f;

    // gather A(t) into buffer t&1: warp -> 8 pixels, lanes -> 32 channels
    auto gatherA = [&](int tt) {
        const int kk = tt >> 3;
        const float* xTc = xTl + (tt & 7) * 32;
        const uint32_t Aw = sb + FSM_A + (tt & 1) * 8192;
#pragma unroll
        for (int i = 0; i < 8; i++) {
            int p = warp * 8 + i;
            int mi = p * 9 + kk;
            int bs = sbse[mi];
            float4 w4 = swt[mi];
            const float* tp = xTc + bs;
            float v = w4.x * __ldg(tp)
                    + w4.y * __ldg(tp + 256)
                    + w4.z * __ldg(tp + ROWE)
                    + w4.w * __ldg(tp + ROWE + 256);
            sts32(Aw + p * 128 + (lswz ^ ((uint32_t)(p & 7) << 4)), to_tf32(v));
        }
    };

#pragma unroll 1
    for (int t = NT0; t < NT1; t++) {
        gatherA(t);                                    // A(t) -> buf t&1

        asm volatile("cp.async.wait_group 0;" ::: "memory");  // B(t) done
        __syncthreads();   // A(t) visible; all warps past mma(t-1)

        if (t + 1 < NT1) LOAD_B(t + 1);                // stage (t+1)&1 free now
        asm volatile("cp.async.commit_group;" ::: "memory");

        const uint32_t As = sb + FSM_A + (t & 1) * 8192;
        const uint32_t Bs = sb + FSM_B + (t & 1) * 32768;

#pragma unroll
        for (int ks = 0; ks < 4; ks++) {
            const int ch = ks * 2 + (tg >> 1);
            const int hb = (tg & 1) << 3;

            uint32_t a[2][4];
#pragma unroll
            for (int mt = 0; mt < 2; mt++) {
                int r1 = wm + mt * 16 + g;
                int r2 = r1 + 8;
                uint32_t ad1 = As + r1 * 128 + ((ch ^ (r1 & 7)) << 4) + hb;
                uint32_t ad2 = As + r2 * 128 + ((ch ^ (r2 & 7)) << 4) + hb;
                asm volatile("ld.shared.v2.b32 {%0,%1}, [%2];"
                             : "=r"(a[mt][0]), "=r"(a[mt][2]) : "r"(ad1));
                asm volatile("ld.shared.v2.b32 {%0,%1}, [%2];"
                             : "=r"(a[mt][1]), "=r"(a[mt][3]) : "r"(ad2));
            }
#pragma unroll
            for (int nt = 0; nt < 8; nt++) {
                int rr = wn + nt * 8 + g;
                uint32_t bd = Bs + rr * 128 + ((ch ^ (rr & 7)) << 4) + hb;
                uint32_t b[2];
                asm volatile("ld.shared.v2.b32 {%0,%1}, [%2];"
                             : "=r"(b[0]), "=r"(b[1]) : "r"(bd));
                MMA_TF32(c[0][nt], a[0], b);
                MMA_TF32(c[1][nt], a[1], b);
            }
        }
    }

    // ---- epilogue: write partial (same layout as out) ----
    float* ob = g_part + (size_t)kb * PARTSZ
              + (size_t)nimg * OC * 4096 + (m0 & 4095);
#pragma unroll
    for (int mt = 0; mt < 2; mt++) {
        int lm = wm + mt * 16 + g;
#pragma unroll
        for (int nt = 0; nt < 8; nt++) {
            int o = wn + nt * 8 + tg * 2;
            ob[(size_t)o * 4096 + lm]           = c[mt][nt][0];
            ob[(size_t)(o + 1) * 4096 + lm]     = c[mt][nt][1];
            ob[(size_t)o * 4096 + lm + 8]       = c[mt][nt][2];
            ob[(size_t)(o + 1) * 4096 + lm + 8] = c[mt][nt][3];
        }
    }
}

// ---------------------------------------------------------------------------
// K5: add partials -> out
// ---------------------------------------------------------------------------
__global__ __launch_bounds__(256) void add_parts_kernel(float* __restrict__ out)
{
    size_t i = ((size_t)blockIdx.x * 256 + threadIdx.x) * 4;
    float4 a = *(const float4*)(g_part + i);
    float4 b = *(const float4*)(g_part + PARTSZ + i);
    float4 r;
    r.x = a.x + b.x; r.y = a.y + b.y; r.z = a.z + b.z; r.w = a.w + b.w;
    *(float4*)(out + i) = r;
}

// ---------------------------------------------------------------------------
extern "C" void kernel_launch(void* const* d_in, const int* in_sizes, int n_in,
                              void* d_out, int out_size)
{
    const float* x      = (const float*)d_in[0];
    const float* conv_w = (const float*)d_in[1];
    const float* conv_b = (const float*)d_in[2];
    const float* dcn_w  = (const float*)d_in[3];
    float* out = (float*)d_out;

    cudaFuncSetAttribute(offset_gemm_kernel,
                         cudaFuncAttributeMaxDynamicSharedMemorySize, OFF_SMEM);
    cudaFuncSetAttribute(fused_gemm_kernel,
                         cudaFuncAttributeMaxDynamicSharedMemorySize, FUSED_SMEM);

    transpose_x_kernel<<<dim3(PXW, NN), 256>>>(x);
    permute_w_kernel<<<OC, 256>>>(dcn_w);
    permute_woff_kernel<<<32, 256>>>(conv_w);
    offset_gemm_kernel<<<MDIM / 128, 256, OFF_SMEM>>>(x, conv_b);
    fused_gemm_kernel<<<MDIM / 64 * 2, 256, FUSED_SMEM>>>();
    add_parts_kernel<<<(int)(PARTSZ / 1024), 256>>>(out);
}

// round 15
// speedup vs baseline: 1.2463x; 1.2463x over previous
#include <cuda_runtime.h>
#include <cuda_bf16.h>
#include <math.h>
#include <cstdint>

// Shapes (fixed)
//   x: (4,256,64,64) f32 | conv_offset_w: (27,256,3,3) | conv_offset_b: (27,)
//   dcn_weight: (256,256,3,3) | out: (4,256,64,64) f32
//
// Pipeline:
//   K2a permute dcn_weight    -> g_wB[o][k']        tf32, k 8-group permuted
//   K2b permute conv_offset_w -> g_wOffHi/Lo[32][k'] split-tf32
//   K3  MERGED kernel, 128 CTAs (BM=128 pixels each):
//        phase 1: offset conv as split-tf32 implicit GEMM -> om in SMEM
//        phase 2: tap metadata (offsets+mask folded) -> SMEM
//        phase 3: fused deformable-sample + tf32 GEMM; gather(t+1) issued
//                 between the barrier and MMA(t) so LSU and tensor overlap.
//
// k-permutation within each 8-group: pos(w) = ((w&3)<<1)|(w>>2) — fragment
// column pair (c, c+4) contiguous -> ld.shared.v2 / st.shared.v2 everywhere.

#define NN 4
#define CC 256
#define HH 64
#define WW 64
#define OC 256
#define KDIM 2304
#define MDIM 16384
#define NTILES 72

__device__ __align__(128) float g_wB[OC * KDIM];
__device__ __align__(128) float g_wOffHi[32 * KDIM];
__device__ __align__(128) float g_wOffLo[32 * KDIM];

__device__ __forceinline__ float to_tf32(float v) {
    uint32_t u;
    asm("cvt.rna.tf32.f32 %0, %1;" : "=r"(u) : "f"(v));
    return __uint_as_float(u);
}
__device__ __forceinline__ uint32_t smem_u32(const void* p) {
    uint32_t a;
    asm("{ .reg .u64 t; cvta.to.shared.u64 t, %1; cvt.u32.u64 %0, t; }"
        : "=r"(a) : "l"(p));
    return a;
}
__device__ __forceinline__ void cp_async16(uint32_t d, const void* s) {
    asm volatile("cp.async.cg.shared.global [%0], [%1], 16;"
                 :: "r"(d), "l"(s) : "memory");
}

#define MMA_TF32(c_, a_, b_)                                                  \
    asm volatile(                                                             \
        "mma.sync.aligned.m16n8k8.row.col.f32.tf32.tf32.f32 "                 \
        "{%0,%1,%2,%3}, {%4,%5,%6,%7}, {%8,%9}, {%0,%1,%2,%3};"               \
        : "+f"((c_)[0]), "+f"((c_)[1]), "+f"((c_)[2]), "+f"((c_)[3])          \
        : "r"((a_)[0]), "r"((a_)[1]), "r"((a_)[2]), "r"((a_)[3]),             \
          "r"((b_)[0]), "r"((b_)[1]))

// ---------------------------------------------------------------------------
// K2a: permute dcn_weight (o,c,kk) -> g_wB[o][k'], tf32-rounded, k-permuted
// ---------------------------------------------------------------------------
__global__ __launch_bounds__(256) void permute_w_kernel(const float* __restrict__ dw)
{
    int o = blockIdx.x;
    int c = threadIdx.x;
    int cp = (c & 0xF8) | ((c & 3) << 1) | ((c >> 2) & 1);
    const float* src = dw + (size_t)(o * CC + c) * 9;
    float* dst = g_wB + (size_t)o * KDIM + cp;
#pragma unroll
    for (int kk = 0; kk < 9; kk++)
        dst[kk * 256] = to_tf32(src[kk]);
}

// ---------------------------------------------------------------------------
// K2b: permute conv_offset_w -> g_wOffHi/Lo[32][k'] (split-tf32)
// ---------------------------------------------------------------------------
__global__ __launch_bounds__(256) void permute_woff_kernel(const float* __restrict__ wo)
{
    int o = blockIdx.x;
    int c = threadIdx.x;
    int cp = (c & 0xF8) | ((c & 3) << 1) | ((c >> 2) & 1);
    float* dh = g_wOffHi + (size_t)o * KDIM + cp;
    float* dl = g_wOffLo + (size_t)o * KDIM + cp;
    if (o < 27) {
        const float* src = wo + (size_t)(o * CC + c) * 9;
#pragma unroll
        for (int kk = 0; kk < 9; kk++) {
            float v = src[kk];
            float h = to_tf32(v);
            dh[kk * 256] = h;
            dl[kk * 256] = to_tf32(v - h);
        }
    } else {
#pragma unroll
        for (int kk = 0; kk < 9; kk++) { dh[kk * 256] = 0.f; dl[kk * 256] = 0.f; }
    }
}

// ---------------------------------------------------------------------------
// K3: MERGED DCN kernel.  128 CTAs, 256 threads, BM=128 (2 y-rows, 1 image).
// smem map (bytes):
//   phase 1: A2 @0 (2x32768) | B1 @65536 (4x8192)            [dead after p1]
//   phase 3: A @0 (2x16384)  | B @32768 (4x32768)
//   moff @163840 (1152*16) | mwt @182272 (1152*16) | om @200704 (27*128*4)
// total 214528  (<= 227KB opt-in)
// ---------------------------------------------------------------------------
#define SM_A    0
#define SM_B    32768
#define OSM_A   0
#define OSM_B   65536
#define SM_MOFF 163840
#define SM_MWT  182272
#define SM_OM   200704
#define DCN_SMEM 214528

__global__ __launch_bounds__(256, 1) void dcn_kernel(
    const float* __restrict__ x, const float* __restrict__ bias,
    float* __restrict__ out)
{
    extern __shared__ __align__(128) char smem[];
    const uint32_t sb = smem_u32(smem);
    const int tid = threadIdx.x;
    const int m0 = blockIdx.x * 128;
    const int nimg = m0 >> 12;
    const int y0 = (m0 & 4095) >> 6;

    const int lane = tid & 31, warp = tid >> 5;
    const int g  = lane >> 2, tg = lane & 3;

    float* om = (float*)(smem + SM_OM);            // [27][128]
    const float* xn = x + (size_t)nimg * CC * 4096;

    // ======================= PHASE 1: offset conv =======================
    {
        const int ldrow = tid >> 3;
        const int ldcol = tid & 7;
        const int swzb  = ldcol ^ (ldrow & 7);
        const char* gBh = (const char*)(g_wOffHi + (size_t)ldrow * KDIM) + ldcol * 16;
        const char* gBl = (const char*)(g_wOffLo + (size_t)ldrow * KDIM) + ldcol * 16;
        const uint32_t dBh = sb + OSM_B + ldrow * 128 + swzb * 16;

#define LOAD_OB(tt_) do {                                                     \
    uint32_t so_ = ((tt_) & 3) * 8192;                                        \
    size_t   ko_ = (size_t)(tt_) * 128;                                       \
    cp_async16(dBh + so_, gBh + ko_);                                         \
    cp_async16(dBh + so_ + 4096, gBl + ko_);                                  \
} while (0)

        LOAD_OB(0); asm volatile("cp.async.commit_group;" ::: "memory");
        LOAD_OB(1); asm volatile("cp.async.commit_group;" ::: "memory");
        LOAD_OB(2); asm volatile("cp.async.commit_group;" ::: "memory");

        const int mloc = tid & 127;
        const int half = tid >> 7;
        const int wm = warp * 16;

        float c[4][4];
#pragma unroll
        for (int i = 0; i < 4; i++)
#pragma unroll
            for (int r = 0; r < 4; r++) c[i][r] = 0.f;

        int soff = 0;
        bool valid = false;
        float R0[16], R1[16];

        auto gather16 = [&](float* R, int tt) {
            if ((tt & 7) == 0) {
                int kk = tt >> 3;
                int yy = y0 + (mloc >> 6) + kk / 3 - 1;
                int xx = (mloc & 63) + kk % 3 - 1;
                valid = ((unsigned)yy < 64u) && ((unsigned)xx < 64u);
                soff = yy * 64 + xx;
            }
            const float* xp = xn + (size_t)((tt & 7) * 32) * 4096;
#pragma unroll
            for (int i = 0; i < 8; i++) {
                int ct = half * 16 + (i >> 2) * 8 + (i & 3);
                R[i * 2]     = valid ? __ldg(xp + (size_t)ct * 4096 + soff) : 0.f;
                R[i * 2 + 1] = valid ? __ldg(xp + (size_t)(ct + 4) * 4096 + soff) : 0.f;
            }
        };
        auto sts16 = [&](const float* R, int tt) {
            const uint32_t Awh = sb + OSM_A + (tt & 1) * 32768 + mloc * 128;
#pragma unroll
            for (int i = 0; i < 8; i++) {
                int q = i & 3;
                int ct = half * 16 + (i >> 2) * 8 + q;
                float v0 = R[i * 2], v1 = R[i * 2 + 1];
                float h0 = to_tf32(v0), l0 = to_tf32(v0 - h0);
                float h1 = to_tf32(v1), l1 = to_tf32(v1 - h1);
                int cp = (ct & 0x18) | (q << 1);
                uint32_t off = ((((uint32_t)cp >> 2) ^ (mloc & 7)) << 4) + ((cp & 3) << 2);
                asm volatile("st.shared.v2.b32 [%0], {%1,%2};"
                             :: "r"(Awh + off),
                                "r"(__float_as_uint(h0)), "r"(__float_as_uint(h1)) : "memory");
                asm volatile("st.shared.v2.b32 [%0], {%1,%2};"
                             :: "r"(Awh + 16384 + off),
                                "r"(__float_as_uint(l0)), "r"(__float_as_uint(l1)) : "memory");
            }
        };
        auto mma_tile = [&](int tt) {
            const uint32_t As = sb + OSM_A + (tt & 1) * 32768;
            const uint32_t Bs = sb + OSM_B + (tt & 3) * 8192;
#pragma unroll
            for (int ks = 0; ks < 4; ks++) {
                const int ch = ks * 2 + (tg >> 1);
                const int hb = (tg & 1) << 3;
                uint32_t ah[4], al[4];
                {
                    int r1 = wm + g, r2 = r1 + 8;
                    uint32_t ad1 = As + r1 * 128 + ((ch ^ (r1 & 7)) << 4) + hb;
                    uint32_t ad2 = As + r2 * 128 + ((ch ^ (r2 & 7)) << 4) + hb;
                    asm volatile("ld.shared.v2.b32 {%0,%1}, [%2];"
                                 : "=r"(ah[0]), "=r"(ah[2]) : "r"(ad1));
                    asm volatile("ld.shared.v2.b32 {%0,%1}, [%2];"
                                 : "=r"(ah[1]), "=r"(ah[3]) : "r"(ad2));
                    asm volatile("ld.shared.v2.b32 {%0,%1}, [%2];"
                                 : "=r"(al[0]), "=r"(al[2]) : "r"(ad1 + 16384));
                    asm volatile("ld.shared.v2.b32 {%0,%1}, [%2];"
                                 : "=r"(al[1]), "=r"(al[3]) : "r"(ad2 + 16384));
                }
#pragma unroll
                for (int nt = 0; nt < 4; nt++) {
                    int rr = nt * 8 + g;
                    uint32_t bd = Bs + rr * 128 + ((ch ^ (rr & 7)) << 4) + hb;
                    uint32_t bh[2], bl[2];
                    asm volatile("ld.shared.v2.b32 {%0,%1}, [%2];"
                                 : "=r"(bh[0]), "=r"(bh[1]) : "r"(bd));
                    asm volatile("ld.shared.v2.b32 {%0,%1}, [%2];"
                                 : "=r"(bl[0]), "=r"(bl[1]) : "r"(bd + 4096));
                    MMA_TF32(c[nt], ah, bh);
                    MMA_TF32(c[nt], ah, bl);
                    MMA_TF32(c[nt], al, bh);
                }
            }
        };

        gather16(R0, 0);

#pragma unroll 1
        for (int t = 0; t < NTILES; t += 2) {
            sts16(R0, t);
            gather16(R1, t + 1);
            asm volatile("cp.async.wait_group 2;" ::: "memory");
            __syncthreads();
            if (t + 3 < NTILES) LOAD_OB(t + 3);
            asm volatile("cp.async.commit_group;" ::: "memory");
            mma_tile(t);

            sts16(R1, t + 1);
            if (t + 2 < NTILES) gather16(R0, t + 2);
            asm volatile("cp.async.wait_group 2;" ::: "memory");
            __syncthreads();
            if (t + 4 < NTILES) LOAD_OB(t + 4);
            asm volatile("cp.async.commit_group;" ::: "memory");
            mma_tile(t + 1);
        }

        // epilogue -> smem om[oc][pixel] (+bias)
        int lm = wm + g;
#pragma unroll
        for (int nt = 0; nt < 4; nt++) {
            int oc0 = nt * 8 + tg * 2;
            if (oc0 < 27) {
                float bb = bias[oc0];
                om[oc0 * 128 + lm]     = c[nt][0] + bb;
                om[oc0 * 128 + lm + 8] = c[nt][2] + bb;
            }
            if (oc0 + 1 < 27) {
                float bb = bias[oc0 + 1];
                om[(oc0 + 1) * 128 + lm]     = c[nt][1] + bb;
                om[(oc0 + 1) * 128 + lm + 8] = c[nt][3] + bb;
            }
        }
    }

    // drain phase-1 cp.async (B1 region aliases phase-3 B) + publish om
    asm volatile("cp.async.wait_group 0;" ::: "memory");
    __syncthreads();

    // =================== PHASE 2: B prologue + metadata ===================
    const int ldrow = tid >> 3;
    const int ldcol = tid & 7;
    const int swzb  = ldcol ^ (ldrow & 7);
    const char* gB0 = (const char*)(g_wB + (size_t)ldrow * KDIM) + ldcol * 16;
    const uint32_t dB0 = sb + SM_B + ldrow * 128 + swzb * 16;

#define LOAD_B(tt_) do {                                                      \
    uint32_t so_ = ((tt_) & 3) * 32768;                                       \
    size_t   ko_ = (size_t)(tt_) * 128;                                       \
    _Pragma("unroll")                                                         \
    for (int i_ = 0; i_ < 8; i_++)                                            \
        cp_async16(dB0 + so_ + i_ * 4096,                                     \
                   gB0 + ko_ + (size_t)i_ * 32 * KDIM * 4);                   \
} while (0)

    LOAD_B(0); asm volatile("cp.async.commit_group;" ::: "memory");
    LOAD_B(1); asm volatile("cp.async.commit_group;" ::: "memory");
    LOAD_B(2); asm volatile("cp.async.commit_group;" ::: "memory");

    int4*   moff = (int4*)(smem + SM_MOFF);   // [1152]
    float4* mwt  = (float4*)(smem + SM_MWT);  // [1152]

    for (int idx = tid; idx < 1152; idx += 256) {
        int p128 = idx / 9, kk = idx - p128 * 9;
        int yy = y0 + (p128 >> 6);
        int xx = p128 & 63;
        float oy = om[(2 * kk) * 128 + p128];
        float ox = om[(2 * kk + 1) * 128 + p128];
        float mv = om[(18 + kk) * 128 + p128];
        float m  = 1.f / (1.f + __expf(-mv));

        float py = (float)(yy + kk / 3) + oy;
        float px = (float)(xx + (kk % 3)) + ox;
        py = fminf(fmaxf(py, 0.f), 65.f);
        px = fminf(fmaxf(px, 0.f), 65.f);
        float fy = floorf(py), fx = floorf(px);
        int y1 = (int)fy, x1 = (int)fx;
        float ly = py - fy, lx = px - fx;
        float hy = 1.f - ly, hx = 1.f - lx;
        float wq[4] = { hy * hx, hy * lx, ly * hx, ly * lx };

        int4 o4; float4 w4;
        int   ov[4]; float wv[4];
#pragma unroll
        for (int q = 0; q < 4; q++) {
            int Y = y1 + (q >> 1);
            int X = x1 + (q & 1);
            bool vld = (Y >= 1 && Y <= 64 && X >= 1 && X <= 64);
            int Yc = min(max(Y, 1), 64), Xc = min(max(X, 1), 64);
            ov[q] = (Yc - 1) * 64 + (Xc - 1);
            wv[q] = vld ? wq[q] * m : 0.f;
        }
        o4.x = ov[0]; o4.y = ov[1]; o4.z = ov[2]; o4.w = ov[3];
        w4.x = wv[0]; w4.y = wv[1]; w4.z = wv[2]; w4.w = wv[3];
        moff[idx] = o4;
        mwt[idx]  = w4;
    }
    __syncthreads();

    // ======================= PHASE 3: main fused GEMM =======================
    {
        const int mloc = tid & 127;
        const int half = tid >> 7;
        const int wm = (warp >> 2) * 64;
        const int wn = (warp & 3) * 64;

        float c[4][8][4];
#pragma unroll
        for (int i = 0; i < 4; i++)
#pragma unroll
            for (int j = 0; j < 8; j++)
#pragma unroll
                for (int r = 0; r < 4; r++) c[i][j][r] = 0.f;

        int   ro[4];
        float rw[4];

        auto load_meta = [&](int kk) {
            int4   o4 = moff[mloc * 9 + kk];
            float4 w4 = mwt [mloc * 9 + kk];
            ro[0] = o4.x; ro[1] = o4.y; ro[2] = o4.z; ro[3] = o4.w;
            rw[0] = w4.x; rw[1] = w4.y; rw[2] = w4.z; rw[3] = w4.w;
        };
        auto gather_sts = [&](int tt) {
            const int c0 = (tt & 7) * 32;
            const float* xp = xn + (size_t)c0 * 4096;
            const uint32_t Aw = sb + SM_A + (tt & 1) * 16384 + mloc * 128;
#pragma unroll
            for (int p8 = 0; p8 < 2; p8++) {
#pragma unroll
                for (int q = 0; q < 4; q++) {
                    int ct = half * 16 + p8 * 8 + q;
                    const float* plo = xp + (size_t)ct * 4096;
                    const float* phi = plo + 4 * 4096;
                    float vlo = rw[0] * __ldg(&plo[ro[0]])
                              + rw[1] * __ldg(&plo[ro[1]])
                              + rw[2] * __ldg(&plo[ro[2]])
                              + rw[3] * __ldg(&plo[ro[3]]);
                    float vhi = rw[0] * __ldg(&phi[ro[0]])
                              + rw[1] * __ldg(&phi[ro[1]])
                              + rw[2] * __ldg(&phi[ro[2]])
                              + rw[3] * __ldg(&phi[ro[3]]);
                    int cp = (ct & 0x18) | (q << 1);
                    uint32_t addr = Aw + ((((uint32_t)cp >> 2) ^ (mloc & 7)) << 4)
                                  + ((cp & 3) << 2);
                    asm volatile("st.shared.v2.b32 [%0], {%1,%2};"
                                 :: "r"(addr),
                                    "r"(__float_as_uint(to_tf32(vlo))),
                                    "r"(__float_as_uint(to_tf32(vhi))) : "memory");
                }
            }
        };

        load_meta(0);
        gather_sts(0);            // A(0) -> buf0; visible after first barrier

#pragma unroll 1
        for (int t = 0; t < NTILES; t++) {
            asm volatile("cp.async.wait_group 2;" ::: "memory");
            __syncthreads();      // A(t) visible; B(t) visible; buf (t+1)&1 free

            if (t + 3 < NTILES) LOAD_B(t + 3);
            asm volatile("cp.async.commit_group;" ::: "memory");

            // gather for t+1 issued HERE — overlaps with MMA(t) below
            if (t + 1 < NTILES) {
                if (((t + 1) & 7) == 0) load_meta((t + 1) >> 3);
                gather_sts(t + 1);
            }

            const uint32_t As = sb + SM_A + (t & 1) * 16384;
            const uint32_t Bs = sb + SM_B + (t & 3) * 32768;

#pragma unroll
            for (int ks = 0; ks < 4; ks++) {
                const int ch = ks * 2 + (tg >> 1);
                const int hb = (tg & 1) << 3;

                uint32_t a[4][4];
#pragma unroll
                for (int mt = 0; mt < 4; mt++) {
                    int r1 = wm + mt * 16 + g;
                    int r2 = r1 + 8;
                    uint32_t ad1 = As + r1 * 128 + ((ch ^ (r1 & 7)) << 4) + hb;
                    uint32_t ad2 = As + r2 * 128 + ((ch ^ (r2 & 7)) << 4) + hb;
                    asm volatile("ld.shared.v2.b32 {%0,%1}, [%2];"
                                 : "=r"(a[mt][0]), "=r"(a[mt][2]) : "r"(ad1));
                    asm volatile("ld.shared.v2.b32 {%0,%1}, [%2];"
                                 : "=r"(a[mt][1]), "=r"(a[mt][3]) : "r"(ad2));
                }
#pragma unroll
                for (int nt = 0; nt < 8; nt++) {
                    int rr = wn + nt * 8 + g;
                    uint32_t bd = Bs + rr * 128 + ((ch ^ (rr & 7)) << 4) + hb;
                    uint32_t b[2];
                    asm volatile("ld.shared.v2.b32 {%0,%1}, [%2];"
                                 : "=r"(b[0]), "=r"(b[1]) : "r"(bd));
#pragma unroll
                    for (int mt = 0; mt < 4; mt++)
                        MMA_TF32(c[mt][nt], a[mt], b);
                }
            }
        }

        // ---- epilogue ----
        float* ob = out + (size_t)nimg * OC * 4096 + (m0 & 4095);
#pragma unroll
        for (int mt = 0; mt < 4; mt++) {
            int lm = wm + mt * 16 + g;
#pragma unroll
            for (int nt = 0; nt < 8; nt++) {
                int o = wn + nt * 8 + tg * 2;
                ob[(size_t)o * 4096 + lm]           = c[mt][nt][0];
                ob[(size_t)(o + 1) * 4096 + lm]     = c[mt][nt][1];
                ob[(size_t)o * 4096 + lm + 8]       = c[mt][nt][2];
                ob[(size_t)(o + 1) * 4096 + lm + 8] = c[mt][nt][3];
            }
        }
    }
}

// ---------------------------------------------------------------------------
extern "C" void kernel_launch(void* const* d_in, const int* in_sizes, int n_in,
                              void* d_out, int out_size)
{
    const float* x      = (const float*)d_in[0];
    const float* conv_w = (const float*)d_in[1];
    const float* conv_b = (const float*)d_in[2];
    const float* dcn_w  = (const float*)d_in[3];
    float* out = (float*)d_out;

    cudaFuncSetAttribute(dcn_kernel,
                         cudaFuncAttributeMaxDynamicSharedMemorySize, DCN_SMEM);

    permute_w_kernel<<<OC, 256>>>(dcn_w);
    permute_woff_kernel<<<32, 256>>>(conv_w);
    dcn_kernel<<<MDIM / 128, 256, DCN_SMEM>>>(x, conv_b, out);
}

// round 16
// speedup vs baseline: 1.3348x; 1.0710x over previous
#include <cuda_runtime.h>
#include <cuda_bf16.h>
#include <math.h>
#include <cstdint>

// Shapes (fixed)
//   x: (4,256,64,64) f32 | conv_offset_w: (27,256,3,3) | conv_offset_b: (27,)
//   dcn_weight: (256,256,3,3) | out: (4,256,64,64) f32
//
// Pipeline:
//   K2a permute dcn_weight    -> g_wB[o][k']        tf32, k 8-group permuted
//   K2b permute conv_offset_w -> g_wOffHi/Lo[32][k'] split-tf32
//   K3  MERGED kernel, 128 CTAs (BM=128 pixels each):
//        phase 1: offset conv (split-tf32 implicit GEMM) -> om in SMEM
//        phase 2: tap metadata -> SMEM
//        phase 3: fused sample+GEMM; gather for tile t+1 SOFTWARE-PIPELINED
//                 in 4 parts interleaved with the 4 ks MMA sub-steps of
//                 tile t (issue LDGs -> MMA covers latency -> FMA+STS).
//
// k-permutation within each 8-group: pos(w) = ((w&3)<<1)|(w>>2).

#define NN 4
#define CC 256
#define HH 64
#define WW 64
#define OC 256
#define KDIM 2304
#define MDIM 16384
#define NTILES 72

__device__ __align__(128) float g_wB[OC * KDIM];
__device__ __align__(128) float g_wOffHi[32 * KDIM];
__device__ __align__(128) float g_wOffLo[32 * KDIM];

__device__ __forceinline__ float to_tf32(float v) {
    uint32_t u;
    asm("cvt.rna.tf32.f32 %0, %1;" : "=r"(u) : "f"(v));
    return __uint_as_float(u);
}
__device__ __forceinline__ uint32_t smem_u32(const void* p) {
    uint32_t a;
    asm("{ .reg .u64 t; cvta.to.shared.u64 t, %1; cvt.u32.u64 %0, t; }"
        : "=r"(a) : "l"(p));
    return a;
}
__device__ __forceinline__ void cp_async16(uint32_t d, const void* s) {
    asm volatile("cp.async.cg.shared.global [%0], [%1], 16;"
                 :: "r"(d), "l"(s) : "memory");
}

#define MMA_TF32(c_, a_, b_)                                                  \
    asm volatile(                                                             \
        "mma.sync.aligned.m16n8k8.row.col.f32.tf32.tf32.f32 "                 \
        "{%0,%1,%2,%3}, {%4,%5,%6,%7}, {%8,%9}, {%0,%1,%2,%3};"               \
        : "+f"((c_)[0]), "+f"((c_)[1]), "+f"((c_)[2]), "+f"((c_)[3])          \
        : "r"((a_)[0]), "r"((a_)[1]), "r"((a_)[2]), "r"((a_)[3]),             \
          "r"((b_)[0]), "r"((b_)[1]))

// ---------------------------------------------------------------------------
// K2a: permute dcn_weight (o,c,kk) -> g_wB[o][k'], tf32-rounded, k-permuted
// ---------------------------------------------------------------------------
__global__ __launch_bounds__(256) void permute_w_kernel(const float* __restrict__ dw)
{
    int o = blockIdx.x;
    int c = threadIdx.x;
    int cp = (c & 0xF8) | ((c & 3) << 1) | ((c >> 2) & 1);
    const float* src = dw + (size_t)(o * CC + c) * 9;
    float* dst = g_wB + (size_t)o * KDIM + cp;
#pragma unroll
    for (int kk = 0; kk < 9; kk++)
        dst[kk * 256] = to_tf32(src[kk]);
}

// ---------------------------------------------------------------------------
// K2b: permute conv_offset_w -> g_wOffHi/Lo[32][k'] (split-tf32)
// ---------------------------------------------------------------------------
__global__ __launch_bounds__(256) void permute_woff_kernel(const float* __restrict__ wo)
{
    int o = blockIdx.x;
    int c = threadIdx.x;
    int cp = (c & 0xF8) | ((c & 3) << 1) | ((c >> 2) & 1);
    float* dh = g_wOffHi + (size_t)o * KDIM + cp;
    float* dl = g_wOffLo + (size_t)o * KDIM + cp;
    if (o < 27) {
        const float* src = wo + (size_t)(o * CC + c) * 9;
#pragma unroll
        for (int kk = 0; kk < 9; kk++) {
            float v = src[kk];
            float h = to_tf32(v);
            dh[kk * 256] = h;
            dl[kk * 256] = to_tf32(v - h);
        }
    } else {
#pragma unroll
        for (int kk = 0; kk < 9; kk++) { dh[kk * 256] = 0.f; dl[kk * 256] = 0.f; }
    }
}

// ---------------------------------------------------------------------------
// K3: MERGED DCN kernel.  128 CTAs, 256 threads, BM=128 (2 y-rows, 1 image).
// smem map (bytes):
//   phase 1: A2 @0 (2x32768) | B1 @65536 (4x8192)            [dead after p1]
//   phase 3: A @0 (2x16384)  | B @32768 (4x32768)
//   moff @163840 | mwt @182272 | om @200704 (27*128*4)
// total 214528
// ---------------------------------------------------------------------------
#define SM_A    0
#define SM_B    32768
#define OSM_A   0
#define OSM_B   65536
#define SM_MOFF 163840
#define SM_MWT  182272
#define SM_OM   200704
#define DCN_SMEM 214528

__global__ __launch_bounds__(256, 1) void dcn_kernel(
    const float* __restrict__ x, const float* __restrict__ bias,
    float* __restrict__ out)
{
    extern __shared__ __align__(128) char smem[];
    const uint32_t sb = smem_u32(smem);
    const int tid = threadIdx.x;
    const int m0 = blockIdx.x * 128;
    const int nimg = m0 >> 12;
    const int y0 = (m0 & 4095) >> 6;

    const int lane = tid & 31, warp = tid >> 5;
    const int g  = lane >> 2, tg = lane & 3;

    float* om = (float*)(smem + SM_OM);            // [27][128]
    const float* xn = x + (size_t)nimg * CC * 4096;

    // ======================= PHASE 1: offset conv =======================
    {
        const int ldrow = tid >> 3;
        const int ldcol = tid & 7;
        const int swzb  = ldcol ^ (ldrow & 7);
        const char* gBh = (const char*)(g_wOffHi + (size_t)ldrow * KDIM) + ldcol * 16;
        const char* gBl = (const char*)(g_wOffLo + (size_t)ldrow * KDIM) + ldcol * 16;
        const uint32_t dBh = sb + OSM_B + ldrow * 128 + swzb * 16;

#define LOAD_OB(tt_) do {                                                     \
    uint32_t so_ = ((tt_) & 3) * 8192;                                        \
    size_t   ko_ = (size_t)(tt_) * 128;                                       \
    cp_async16(dBh + so_, gBh + ko_);                                         \
    cp_async16(dBh + so_ + 4096, gBl + ko_);                                  \
} while (0)

        LOAD_OB(0); asm volatile("cp.async.commit_group;" ::: "memory");
        LOAD_OB(1); asm volatile("cp.async.commit_group;" ::: "memory");
        LOAD_OB(2); asm volatile("cp.async.commit_group;" ::: "memory");

        const int mloc = tid & 127;
        const int half = tid >> 7;
        const int wm = warp * 16;

        float c[4][4];
#pragma unroll
        for (int i = 0; i < 4; i++)
#pragma unroll
            for (int r = 0; r < 4; r++) c[i][r] = 0.f;

        int soff = 0;
        bool valid = false;
        float R0[16], R1[16];

        auto gather16 = [&](float* R, int tt) {
            if ((tt & 7) == 0) {
                int kk = tt >> 3;
                int yy = y0 + (mloc >> 6) + kk / 3 - 1;
                int xx = (mloc & 63) + kk % 3 - 1;
                valid = ((unsigned)yy < 64u) && ((unsigned)xx < 64u);
                soff = yy * 64 + xx;
            }
            const float* xp = xn + (size_t)((tt & 7) * 32) * 4096;
#pragma unroll
            for (int i = 0; i < 8; i++) {
                int ct = half * 16 + (i >> 2) * 8 + (i & 3);
                R[i * 2]     = valid ? __ldg(xp + (size_t)ct * 4096 + soff) : 0.f;
                R[i * 2 + 1] = valid ? __ldg(xp + (size_t)(ct + 4) * 4096 + soff) : 0.f;
            }
        };
        auto sts16 = [&](const float* R, int tt) {
            const uint32_t Awh = sb + OSM_A + (tt & 1) * 32768 + mloc * 128;
#pragma unroll
            for (int i = 0; i < 8; i++) {
                int q = i & 3;
                int ct = half * 16 + (i >> 2) * 8 + q;
                float v0 = R[i * 2], v1 = R[i * 2 + 1];
                float h0 = to_tf32(v0), l0 = to_tf32(v0 - h0);
                float h1 = to_tf32(v1), l1 = to_tf32(v1 - h1);
                int cp = (ct & 0x18) | (q << 1);
                uint32_t off = ((((uint32_t)cp >> 2) ^ (mloc & 7)) << 4) + ((cp & 3) << 2);
                asm volatile("st.shared.v2.b32 [%0], {%1,%2};"
                             :: "r"(Awh + off),
                                "r"(__float_as_uint(h0)), "r"(__float_as_uint(h1)) : "memory");
                asm volatile("st.shared.v2.b32 [%0], {%1,%2};"
                             :: "r"(Awh + 16384 + off),
                                "r"(__float_as_uint(l0)), "r"(__float_as_uint(l1)) : "memory");
            }
        };
        auto mma_tile = [&](int tt) {
            const uint32_t As = sb + OSM_A + (tt & 1) * 32768;
            const uint32_t Bs = sb + OSM_B + (tt & 3) * 8192;
#pragma unroll
            for (int ks = 0; ks < 4; ks++) {
                const int ch = ks * 2 + (tg >> 1);
                const int hb = (tg & 1) << 3;
                uint32_t ah[4], al[4];
                {
                    int r1 = wm + g, r2 = r1 + 8;
                    uint32_t ad1 = As + r1 * 128 + ((ch ^ (r1 & 7)) << 4) + hb;
                    uint32_t ad2 = As + r2 * 128 + ((ch ^ (r2 & 7)) << 4) + hb;
                    asm volatile("ld.shared.v2.b32 {%0,%1}, [%2];"
                                 : "=r"(ah[0]), "=r"(ah[2]) : "r"(ad1));
                    asm volatile("ld.shared.v2.b32 {%0,%1}, [%2];"
                                 : "=r"(ah[1]), "=r"(ah[3]) : "r"(ad2));
                    asm volatile("ld.shared.v2.b32 {%0,%1}, [%2];"
                                 : "=r"(al[0]), "=r"(al[2]) : "r"(ad1 + 16384));
                    asm volatile("ld.shared.v2.b32 {%0,%1}, [%2];"
                                 : "=r"(al[1]), "=r"(al[3]) : "r"(ad2 + 16384));
                }
#pragma unroll
                for (int nt = 0; nt < 4; nt++) {
                    int rr = nt * 8 + g;
                    uint32_t bd = Bs + rr * 128 + ((ch ^ (rr & 7)) << 4) + hb;
                    uint32_t bh[2], bl[2];
                    asm volatile("ld.shared.v2.b32 {%0,%1}, [%2];"
                                 : "=r"(bh[0]), "=r"(bh[1]) : "r"(bd));
                    asm volatile("ld.shared.v2.b32 {%0,%1}, [%2];"
                                 : "=r"(bl[0]), "=r"(bl[1]) : "r"(bd + 4096));
                    MMA_TF32(c[nt], ah, bh);
                    MMA_TF32(c[nt], ah, bl);
                    MMA_TF32(c[nt], al, bh);
                }
            }
        };

        gather16(R0, 0);

#pragma unroll 1
        for (int t = 0; t < NTILES; t += 2) {
            sts16(R0, t);
            gather16(R1, t + 1);
            asm volatile("cp.async.wait_group 2;" ::: "memory");
            __syncthreads();
            if (t + 3 < NTILES) LOAD_OB(t + 3);
            asm volatile("cp.async.commit_group;" ::: "memory");
            mma_tile(t);

            sts16(R1, t + 1);
            if (t + 2 < NTILES) gather16(R0, t + 2);
            asm volatile("cp.async.wait_group 2;" ::: "memory");
            __syncthreads();
            if (t + 4 < NTILES) LOAD_OB(t + 4);
            asm volatile("cp.async.commit_group;" ::: "memory");
            mma_tile(t + 1);
        }

        // epilogue -> smem om[oc][pixel] (+bias)
        int lm = wm + g;
#pragma unroll
        for (int nt = 0; nt < 4; nt++) {
            int oc0 = nt * 8 + tg * 2;
            if (oc0 < 27) {
                float bb = bias[oc0];
                om[oc0 * 128 + lm]     = c[nt][0] + bb;
                om[oc0 * 128 + lm + 8] = c[nt][2] + bb;
            }
            if (oc0 + 1 < 27) {
                float bb = bias[oc0 + 1];
                om[(oc0 + 1) * 128 + lm]     = c[nt][1] + bb;
                om[(oc0 + 1) * 128 + lm + 8] = c[nt][3] + bb;
            }
        }
    }

    // drain phase-1 cp.async (B1 region aliases phase-3 B) + publish om
    asm volatile("cp.async.wait_group 0;" ::: "memory");
    __syncthreads();

    // =================== PHASE 2: B prologue + metadata ===================
    const int ldrow = tid >> 3;
    const int ldcol = tid & 7;
    const int swzb  = ldcol ^ (ldrow & 7);
    const char* gB0 = (const char*)(g_wB + (size_t)ldrow * KDIM) + ldcol * 16;
    const uint32_t dB0 = sb + SM_B + ldrow * 128 + swzb * 16;

#define LOAD_B(tt_) do {                                                      \
    uint32_t so_ = ((tt_) & 3) * 32768;                                       \
    size_t   ko_ = (size_t)(tt_) * 128;                                       \
    _Pragma("unroll")                                                         \
    for (int i_ = 0; i_ < 8; i_++)                                            \
        cp_async16(dB0 + so_ + i_ * 4096,                                     \
                   gB0 + ko_ + (size_t)i_ * 32 * KDIM * 4);                   \
} while (0)

    LOAD_B(0); asm volatile("cp.async.commit_group;" ::: "memory");
    LOAD_B(1); asm volatile("cp.async.commit_group;" ::: "memory");
    LOAD_B(2); asm volatile("cp.async.commit_group;" ::: "memory");

    int4*   moff = (int4*)(smem + SM_MOFF);   // [1152]
    float4* mwt  = (float4*)(smem + SM_MWT);  // [1152]

    for (int idx = tid; idx < 1152; idx += 256) {
        int p128 = idx / 9, kk = idx - p128 * 9;
        int yy = y0 + (p128 >> 6);
        int xx = p128 & 63;
        float oy = om[(2 * kk) * 128 + p128];
        float ox = om[(2 * kk + 1) * 128 + p128];
        float mv = om[(18 + kk) * 128 + p128];
        float m  = 1.f / (1.f + __expf(-mv));

        float py = (float)(yy + kk / 3) + oy;
        float px = (float)(xx + (kk % 3)) + ox;
        py = fminf(fmaxf(py, 0.f), 65.f);
        px = fminf(fmaxf(px, 0.f), 65.f);
        float fy = floorf(py), fx = floorf(px);
        int y1 = (int)fy, x1 = (int)fx;
        float ly = py - fy, lx = px - fx;
        float hy = 1.f - ly, hx = 1.f - lx;
        float wq[4] = { hy * hx, hy * lx, ly * hx, ly * lx };

        int4 o4; float4 w4;
        int   ov[4]; float wv[4];
#pragma unroll
        for (int q = 0; q < 4; q++) {
            int Y = y1 + (q >> 1);
            int X = x1 + (q & 1);
            bool vld = (Y >= 1 && Y <= 64 && X >= 1 && X <= 64);
            int Yc = min(max(Y, 1), 64), Xc = min(max(X, 1), 64);
            ov[q] = (Yc - 1) * 64 + (Xc - 1);
            wv[q] = vld ? wq[q] * m : 0.f;
        }
        o4.x = ov[0]; o4.y = ov[1]; o4.z = ov[2]; o4.w = ov[3];
        w4.x = wv[0]; w4.y = wv[1]; w4.z = wv[2]; w4.w = wv[3];
        moff[idx] = o4;
        mwt[idx]  = w4;
    }
    __syncthreads();

    // ======================= PHASE 3: main fused GEMM =======================
    {
        const int mloc = tid & 127;
        const int half = tid >> 7;
        const int wm = (warp >> 2) * 64;
        const int wn = (warp & 3) * 64;

        float c[4][8][4];
#pragma unroll
        for (int i = 0; i < 4; i++)
#pragma unroll
            for (int j = 0; j < 8; j++)
#pragma unroll
                for (int r = 0; r < 4; r++) c[i][j][r] = 0.f;

        int   ro[4];
        float rw[4];
        float T[16];              // raw taps for one gather part (4 values)

        auto load_meta = [&](int kk) {
            int4   o4 = moff[mloc * 9 + kk];
            float4 w4 = mwt [mloc * 9 + kk];
            ro[0] = o4.x; ro[1] = o4.y; ro[2] = o4.z; ro[3] = o4.w;
            rw[0] = w4.x; rw[1] = w4.y; rw[2] = w4.z; rw[3] = w4.w;
        };
        // issue raw tap LDGs for part j (value pairs i = 2j, 2j+1) of tile tt
        auto issue_part = [&](int tt, int j) {
            const float* xp = xn + (size_t)((tt & 7) * 32) * 4096;
#pragma unroll
            for (int u = 0; u < 2; u++) {
                int i = j * 2 + u;
                int ct = half * 16 + (i >> 2) * 8 + (i & 3);
                const float* plo = xp + (size_t)ct * 4096;
                const float* phi = plo + 4 * 4096;
#pragma unroll
                for (int q2 = 0; q2 < 4; q2++) {
                    T[u * 8 + q2]     = __ldg(&plo[ro[q2]]);
                    T[u * 8 + 4 + q2] = __ldg(&phi[ro[q2]]);
                }
            }
        };
        // combine + STS for part j of tile tt
        auto consume_part = [&](int tt, int j) {
            const uint32_t Aw = sb + SM_A + (tt & 1) * 16384 + mloc * 128;
#pragma unroll
            for (int u = 0; u < 2; u++) {
                int i = j * 2 + u;
                int ct = half * 16 + (i >> 2) * 8 + (i & 3);
                float vlo = rw[0] * T[u * 8 + 0] + rw[1] * T[u * 8 + 1]
                          + rw[2] * T[u * 8 + 2] + rw[3] * T[u * 8 + 3];
                float vhi = rw[0] * T[u * 8 + 4] + rw[1] * T[u * 8 + 5]
                          + rw[2] * T[u * 8 + 6] + rw[3] * T[u * 8 + 7];
                int cp = (ct & 0x18) | ((i & 3) << 1);
                uint32_t addr = Aw + ((((uint32_t)cp >> 2) ^ (mloc & 7)) << 4)
                              + ((cp & 3) << 2);
                asm volatile("st.shared.v2.b32 [%0], {%1,%2};"
                             :: "r"(addr),
                                "r"(__float_as_uint(to_tf32(vlo))),
                                "r"(__float_as_uint(to_tf32(vhi))) : "memory");
            }
        };
        // one ks sub-step of MMA(t)
        auto mma_ks = [&](uint32_t As, uint32_t Bs, int ks) {
            const int ch = ks * 2 + (tg >> 1);
            const int hb = (tg & 1) << 3;
            uint32_t a[4][4];
#pragma unroll
            for (int mt = 0; mt < 4; mt++) {
                int r1 = wm + mt * 16 + g;
                int r2 = r1 + 8;
                uint32_t ad1 = As + r1 * 128 + ((ch ^ (r1 & 7)) << 4) + hb;
                uint32_t ad2 = As + r2 * 128 + ((ch ^ (r2 & 7)) << 4) + hb;
                asm volatile("ld.shared.v2.b32 {%0,%1}, [%2];"
                             : "=r"(a[mt][0]), "=r"(a[mt][2]) : "r"(ad1));
                asm volatile("ld.shared.v2.b32 {%0,%1}, [%2];"
                             : "=r"(a[mt][1]), "=r"(a[mt][3]) : "r"(ad2));
            }
#pragma unroll
            for (int nt = 0; nt < 8; nt++) {
                int rr = wn + nt * 8 + g;
                uint32_t bd = Bs + rr * 128 + ((ch ^ (rr & 7)) << 4) + hb;
                uint32_t b[2];
                asm volatile("ld.shared.v2.b32 {%0,%1}, [%2];"
                             : "=r"(b[0]), "=r"(b[1]) : "r"(bd));
#pragma unroll
                for (int mt = 0; mt < 4; mt++)
                    MMA_TF32(c[mt][nt], a[mt], b);
            }
        };

        // prologue: full gather of tile 0 (register-split, back to back)
        load_meta(0);
#pragma unroll
        for (int j = 0; j < 4; j++) { issue_part(0, j); consume_part(0, j); }

#pragma unroll 1
        for (int t = 0; t < NTILES; t++) {
            asm volatile("cp.async.wait_group 2;" ::: "memory");
            __syncthreads();      // A(t) & B(t) visible; buf (t+1)&1 free

            if (t + 3 < NTILES) LOAD_B(t + 3);
            asm volatile("cp.async.commit_group;" ::: "memory");

            const uint32_t As = sb + SM_A + (t & 1) * 16384;
            const uint32_t Bs = sb + SM_B + (t & 3) * 32768;
            const bool nx = (t + 1 < NTILES);

            if (nx) {
                if (((t + 1) & 7) == 0) load_meta((t + 1) >> 3);
                issue_part(t + 1, 0);        // LDGs in flight during ks=0
            }
            mma_ks(As, Bs, 0);
            if (nx) { consume_part(t + 1, 0); issue_part(t + 1, 1); }
            mma_ks(As, Bs, 1);
            if (nx) { consume_part(t + 1, 1); issue_part(t + 1, 2); }
            mma_ks(As, Bs, 2);
            if (nx) { consume_part(t + 1, 2); issue_part(t + 1, 3); }
            mma_ks(As, Bs, 3);
            if (nx) consume_part(t + 1, 3);
        }

        // ---- epilogue ----
        float* ob = out + (size_t)nimg * OC * 4096 + (m0 & 4095);
#pragma unroll
        for (int mt = 0; mt < 4; mt++) {
            int lm = wm + mt * 16 + g;
#pragma unroll
            for (int nt = 0; nt < 8; nt++) {
                int o = wn + nt * 8 + tg * 2;
                ob[(size_t)o * 4096 + lm]           = c[mt][nt][0];
                ob[(size_t)(o + 1) * 4096 + lm]     = c[mt][nt][1];
                ob[(size_t)o * 4096 + lm + 8]       = c[mt][nt][2];
                ob[(size_t)(o + 1) * 4096 + lm + 8] = c[mt][nt][3];
            }
        }
    }
}

// ---------------------------------------------------------------------------
extern "C" void kernel_launch(void* const* d_in, const int* in_sizes, int n_in,
                              void* d_out, int out_size)
{
    const float* x      = (const float*)d_in[0];
    const float* conv_w = (const float*)d_in[1];
    const float* conv_b = (const float*)d_in[2];
    const float* dcn_w  = (const float*)d_in[3];
    float* out = (float*)d_out;

    cudaFuncSetAttribute(dcn_kernel,
                         cudaFuncAttributeMaxDynamicSharedMemorySize, DCN_SMEM);

    permute_w_kernel<<<OC, 256>>>(dcn_w);
    permute_woff_kernel<<<32, 256>>>(conv_w);
    dcn_kernel<<<MDIM / 128, 256, DCN_SMEM>>>(x, conv_b, out);
}

// round 17
// speedup vs baseline: 1.3536x; 1.0140x over previous
#include <cuda_runtime.h>
#include <cuda_bf16.h>
#include <math.h>
#include <cstdint>

// Shapes (fixed)
//   x: (4,256,64,64) f32 | conv_offset_w: (27,256,3,3) | conv_offset_b: (27,)
//   dcn_weight: (256,256,3,3) | out: (4,256,64,64) f32
//
// Pipeline:
//   K2a permute dcn_weight    -> g_wB[o][k']        tf32, k 8-group permuted
//   K2b permute conv_offset_w -> g_wOffHi/Lo[32][k'] split-tf32
//   K3  MERGED kernel, 128 CTAs (BM=128 pixels each):
//        phase 1: offset conv (split-tf32 implicit GEMM) -> om in SMEM
//        phase 3: fused sample+GEMM; per-kk tap metadata recomputed from om
//                 in registers; gather for tile t+1 software-pipelined in 4
//                 parts between the 4 ks MMA sub-steps of tile t.
//   SMEM kept at 112 KB so L1D retains ~116 KB -> gather taps are L1 hits.
//
// k-permutation within each 8-group: pos(w) = ((w&3)<<1)|(w>>2).

#define NN 4
#define CC 256
#define HH 64
#define WW 64
#define OC 256
#define KDIM 2304
#define MDIM 16384
#define NTILES 72

__device__ __align__(128) float g_wB[OC * KDIM];
__device__ __align__(128) float g_wOffHi[32 * KDIM];
__device__ __align__(128) float g_wOffLo[32 * KDIM];

__device__ __forceinline__ float to_tf32(float v) {
    uint32_t u;
    asm("cvt.rna.tf32.f32 %0, %1;" : "=r"(u) : "f"(v));
    return __uint_as_float(u);
}
__device__ __forceinline__ uint32_t smem_u32(const void* p) {
    uint32_t a;
    asm("{ .reg .u64 t; cvta.to.shared.u64 t, %1; cvt.u32.u64 %0, t; }"
        : "=r"(a) : "l"(p));
    return a;
}
__device__ __forceinline__ void cp_async16(uint32_t d, const void* s) {
    asm volatile("cp.async.cg.shared.global [%0], [%1], 16;"
                 :: "r"(d), "l"(s) : "memory");
}

#define MMA_TF32(c_, a_, b_)                                                  \
    asm volatile(                                                             \
        "mma.sync.aligned.m16n8k8.row.col.f32.tf32.tf32.f32 "                 \
        "{%0,%1,%2,%3}, {%4,%5,%6,%7}, {%8,%9}, {%0,%1,%2,%3};"               \
        : "+f"((c_)[0]), "+f"((c_)[1]), "+f"((c_)[2]), "+f"((c_)[3])          \
        : "r"((a_)[0]), "r"((a_)[1]), "r"((a_)[2]), "r"((a_)[3]),             \
          "r"((b_)[0]), "r"((b_)[1]))

// ---------------------------------------------------------------------------
// K2a: permute dcn_weight (o,c,kk) -> g_wB[o][k'], tf32-rounded, k-permuted
// ---------------------------------------------------------------------------
__global__ __launch_bounds__(256) void permute_w_kernel(const float* __restrict__ dw)
{
    int o = blockIdx.x;
    int c = threadIdx.x;
    int cp = (c & 0xF8) | ((c & 3) << 1) | ((c >> 2) & 1);
    const float* src = dw + (size_t)(o * CC + c) * 9;
    float* dst = g_wB + (size_t)o * KDIM + cp;
#pragma unroll
    for (int kk = 0; kk < 9; kk++)
        dst[kk * 256] = to_tf32(src[kk]);
}

// ---------------------------------------------------------------------------
// K2b: permute conv_offset_w -> g_wOffHi/Lo[32][k'] (split-tf32)
// ---------------------------------------------------------------------------
__global__ __launch_bounds__(256) void permute_woff_kernel(const float* __restrict__ wo)
{
    int o = blockIdx.x;
    int c = threadIdx.x;
    int cp = (c & 0xF8) | ((c & 3) << 1) | ((c >> 2) & 1);
    float* dh = g_wOffHi + (size_t)o * KDIM + cp;
    float* dl = g_wOffLo + (size_t)o * KDIM + cp;
    if (o < 27) {
        const float* src = wo + (size_t)(o * CC + c) * 9;
#pragma unroll
        for (int kk = 0; kk < 9; kk++) {
            float v = src[kk];
            float h = to_tf32(v);
            dh[kk * 256] = h;
            dl[kk * 256] = to_tf32(v - h);
        }
    } else {
#pragma unroll
        for (int kk = 0; kk < 9; kk++) { dh[kk * 256] = 0.f; dl[kk * 256] = 0.f; }
    }
}

// ---------------------------------------------------------------------------
// K3: MERGED DCN kernel.  128 CTAs, 256 threads, BM=128 (2 y-rows, 1 image).
// smem map (bytes):
//   phase 1: A2 @0 (2x32768) | B1 @65536 (4x8192)            [dead after p1]
//   phase 3: A @0 (2x16384)  | B @32768 (2x32768)
//   om @98304 (27*128*4 = 13824)
// total 112128  ->  L1D ~ 116 KB (gather stays L1-resident)
// ---------------------------------------------------------------------------
#define SM_A    0
#define SM_B    32768
#define OSM_A   0
#define OSM_B   65536
#define SM_OM   98304
#define DCN_SMEM 112128

__global__ __launch_bounds__(256, 1) void dcn_kernel(
    const float* __restrict__ x, const float* __restrict__ bias,
    float* __restrict__ out)
{
    extern __shared__ __align__(128) char smem[];
    const uint32_t sb = smem_u32(smem);
    const int tid = threadIdx.x;
    const int m0 = blockIdx.x * 128;
    const int nimg = m0 >> 12;
    const int y0 = (m0 & 4095) >> 6;

    const int lane = tid & 31, warp = tid >> 5;
    const int g  = lane >> 2, tg = lane & 3;

    float* om = (float*)(smem + SM_OM);            // [27][128]
    const float* xn = x + (size_t)nimg * CC * 4096;

    // ======================= PHASE 1: offset conv =======================
    {
        const int ldrow = tid >> 3;
        const int ldcol = tid & 7;
        const int swzb  = ldcol ^ (ldrow & 7);
        const char* gBh = (const char*)(g_wOffHi + (size_t)ldrow * KDIM) + ldcol * 16;
        const char* gBl = (const char*)(g_wOffLo + (size_t)ldrow * KDIM) + ldcol * 16;
        const uint32_t dBh = sb + OSM_B + ldrow * 128 + swzb * 16;

#define LOAD_OB(tt_) do {                                                     \
    uint32_t so_ = ((tt_) & 3) * 8192;                                        \
    size_t   ko_ = (size_t)(tt_) * 128;                                       \
    cp_async16(dBh + so_, gBh + ko_);                                         \
    cp_async16(dBh + so_ + 4096, gBl + ko_);                                  \
} while (0)

        LOAD_OB(0); asm volatile("cp.async.commit_group;" ::: "memory");
        LOAD_OB(1); asm volatile("cp.async.commit_group;" ::: "memory");
        LOAD_OB(2); asm volatile("cp.async.commit_group;" ::: "memory");

        const int mloc = tid & 127;
        const int half = tid >> 7;
        const int wm = warp * 16;

        float c[4][4];
#pragma unroll
        for (int i = 0; i < 4; i++)
#pragma unroll
            for (int r = 0; r < 4; r++) c[i][r] = 0.f;

        int soff = 0;
        bool valid = false;
        float R0[16], R1[16];

        auto gather16 = [&](float* R, int tt) {
            if ((tt & 7) == 0) {
                int kk = tt >> 3;
                int yy = y0 + (mloc >> 6) + kk / 3 - 1;
                int xx = (mloc & 63) + kk % 3 - 1;
                valid = ((unsigned)yy < 64u) && ((unsigned)xx < 64u);
                soff = yy * 64 + xx;
            }
            const float* xp = xn + (size_t)((tt & 7) * 32) * 4096;
#pragma unroll
            for (int i = 0; i < 8; i++) {
                int ct = half * 16 + (i >> 2) * 8 + (i & 3);
                R[i * 2]     = valid ? __ldg(xp + (size_t)ct * 4096 + soff) : 0.f;
                R[i * 2 + 1] = valid ? __ldg(xp + (size_t)(ct + 4) * 4096 + soff) : 0.f;
            }
        };
        auto sts16 = [&](const float* R, int tt) {
            const uint32_t Awh = sb + OSM_A + (tt & 1) * 32768 + mloc * 128;
#pragma unroll
            for (int i = 0; i < 8; i++) {
                int q = i & 3;
                int ct = half * 16 + (i >> 2) * 8 + q;
                float v0 = R[i * 2], v1 = R[i * 2 + 1];
                float h0 = to_tf32(v0), l0 = to_tf32(v0 - h0);
                float h1 = to_tf32(v1), l1 = to_tf32(v1 - h1);
                int cp = (ct & 0x18) | (q << 1);
                uint32_t off = ((((uint32_t)cp >> 2) ^ (mloc & 7)) << 4) + ((cp & 3) << 2);
                asm volatile("st.shared.v2.b32 [%0], {%1,%2};"
                             :: "r"(Awh + off),
                                "r"(__float_as_uint(h0)), "r"(__float_as_uint(h1)) : "memory");
                asm volatile("st.shared.v2.b32 [%0], {%1,%2};"
                             :: "r"(Awh + 16384 + off),
                                "r"(__float_as_uint(l0)), "r"(__float_as_uint(l1)) : "memory");
            }
        };
        auto mma_tile = [&](int tt) {
            const uint32_t As = sb + OSM_A + (tt & 1) * 32768;
            const uint32_t Bs = sb + OSM_B + (tt & 3) * 8192;
#pragma unroll
            for (int ks = 0; ks < 4; ks++) {
                const int ch = ks * 2 + (tg >> 1);
                const int hb = (tg & 1) << 3;
                uint32_t ah[4], al[4];
                {
                    int r1 = wm + g, r2 = r1 + 8;
                    uint32_t ad1 = As + r1 * 128 + ((ch ^ (r1 & 7)) << 4) + hb;
                    uint32_t ad2 = As + r2 * 128 + ((ch ^ (r2 & 7)) << 4) + hb;
                    asm volatile("ld.shared.v2.b32 {%0,%1}, [%2];"
                                 : "=r"(ah[0]), "=r"(ah[2]) : "r"(ad1));
                    asm volatile("ld.shared.v2.b32 {%0,%1}, [%2];"
                                 : "=r"(ah[1]), "=r"(ah[3]) : "r"(ad2));
                    asm volatile("ld.shared.v2.b32 {%0,%1}, [%2];"
                                 : "=r"(al[0]), "=r"(al[2]) : "r"(ad1 + 16384));
                    asm volatile("ld.shared.v2.b32 {%0,%1}, [%2];"
                                 : "=r"(al[1]), "=r"(al[3]) : "r"(ad2 + 16384));
                }
#pragma unroll
                for (int nt = 0; nt < 4; nt++) {
                    int rr = nt * 8 + g;
                    uint32_t bd = Bs + rr * 128 + ((ch ^ (rr & 7)) << 4) + hb;
                    uint32_t bh[2], bl[2];
                    asm volatile("ld.shared.v2.b32 {%0,%1}, [%2];"
                                 : "=r"(bh[0]), "=r"(bh[1]) : "r"(bd));
                    asm volatile("ld.shared.v2.b32 {%0,%1}, [%2];"
                                 : "=r"(bl[0]), "=r"(bl[1]) : "r"(bd + 4096));
                    MMA_TF32(c[nt], ah, bh);
                    MMA_TF32(c[nt], ah, bl);
                    MMA_TF32(c[nt], al, bh);
                }
            }
        };

        gather16(R0, 0);

#pragma unroll 1
        for (int t = 0; t < NTILES; t += 2) {
            sts16(R0, t);
            gather16(R1, t + 1);
            asm volatile("cp.async.wait_group 2;" ::: "memory");
            __syncthreads();
            if (t + 3 < NTILES) LOAD_OB(t + 3);
            asm volatile("cp.async.commit_group;" ::: "memory");
            mma_tile(t);

            sts16(R1, t + 1);
            if (t + 2 < NTILES) gather16(R0, t + 2);
            asm volatile("cp.async.wait_group 2;" ::: "memory");
            __syncthreads();
            if (t + 4 < NTILES) LOAD_OB(t + 4);
            asm volatile("cp.async.commit_group;" ::: "memory");
            mma_tile(t + 1);
        }

        // epilogue -> smem om[oc][pixel] (+bias)
        int lm = wm + g;
#pragma unroll
        for (int nt = 0; nt < 4; nt++) {
            int oc0 = nt * 8 + tg * 2;
            if (oc0 < 27) {
                float bb = bias[oc0];
                om[oc0 * 128 + lm]     = c[nt][0] + bb;
                om[oc0 * 128 + lm + 8] = c[nt][2] + bb;
            }
            if (oc0 + 1 < 27) {
                float bb = bias[oc0 + 1];
                om[(oc0 + 1) * 128 + lm]     = c[nt][1] + bb;
                om[(oc0 + 1) * 128 + lm + 8] = c[nt][3] + bb;
            }
        }
    }

    // drain phase-1 cp.async + publish om; phase-1 A/B regions now reusable
    asm volatile("cp.async.wait_group 0;" ::: "memory");
    __syncthreads();

    // ======================= PHASE 3: main fused GEMM =======================
    {
        const int ldrow = tid >> 3;
        const int ldcol = tid & 7;
        const int swzb  = ldcol ^ (ldrow & 7);
        const char* gB0 = (const char*)(g_wB + (size_t)ldrow * KDIM) + ldcol * 16;
        const uint32_t dB0 = sb + SM_B + ldrow * 128 + swzb * 16;

#define LOAD_B(tt_) do {                                                      \
    uint32_t so_ = ((tt_) & 1) * 32768;                                       \
    size_t   ko_ = (size_t)(tt_) * 128;                                       \
    _Pragma("unroll")                                                         \
    for (int i_ = 0; i_ < 8; i_++)                                            \
        cp_async16(dB0 + so_ + i_ * 4096,                                     \
                   gB0 + ko_ + (size_t)i_ * 32 * KDIM * 4);                   \
} while (0)

        LOAD_B(0); asm volatile("cp.async.commit_group;" ::: "memory");

        const int mloc = tid & 127;
        const int half = tid >> 7;
        const int wm = (warp >> 2) * 64;
        const int wn = (warp & 3) * 64;

        float c[4][8][4];
#pragma unroll
        for (int i = 0; i < 4; i++)
#pragma unroll
            for (int j = 0; j < 8; j++)
#pragma unroll
                for (int r = 0; r < 4; r++) c[i][j][r] = 0.f;

        int   ro[4];
        float rw[4];
        float T[16];

        // recompute tap metadata for this thread's pixel at kk (from smem om)
        auto compute_meta = [&](int kk) {
            float oy = om[(2 * kk) * 128 + mloc];
            float ox = om[(2 * kk + 1) * 128 + mloc];
            float mv = om[(18 + kk) * 128 + mloc];
            float m  = 1.f / (1.f + __expf(-mv));
            int yy = y0 + (mloc >> 6);
            int xx = mloc & 63;
            float py = (float)(yy + kk / 3) + oy;
            float px = (float)(xx + (kk % 3)) + ox;
            py = fminf(fmaxf(py, 0.f), 65.f);
            px = fminf(fmaxf(px, 0.f), 65.f);
            float fy = floorf(py), fx = floorf(px);
            int y1 = (int)fy, x1 = (int)fx;
            float ly = py - fy, lx = px - fx;
            float hy = 1.f - ly, hx = 1.f - lx;
            float wq[4] = { hy * hx, hy * lx, ly * hx, ly * lx };
#pragma unroll
            for (int q = 0; q < 4; q++) {
                int Y = y1 + (q >> 1);
                int X = x1 + (q & 1);
                bool vld = (Y >= 1 && Y <= 64 && X >= 1 && X <= 64);
                int Yc = min(max(Y, 1), 64), Xc = min(max(X, 1), 64);
                ro[q] = (Yc - 1) * 64 + (Xc - 1);
                rw[q] = vld ? wq[q] * m : 0.f;
            }
        };
        // issue raw tap LDGs for part j (value pairs i = 2j, 2j+1) of tile tt
        auto issue_part = [&](int tt, int j) {
            const float* xp = xn + (size_t)((tt & 7) * 32) * 4096;
#pragma unroll
            for (int u = 0; u < 2; u++) {
                int i = j * 2 + u;
                int ct = half * 16 + (i >> 2) * 8 + (i & 3);
                const float* plo = xp + (size_t)ct * 4096;
                const float* phi = plo + 4 * 4096;
#pragma unroll
                for (int q2 = 0; q2 < 4; q2++) {
                    T[u * 8 + q2]     = __ldg(&plo[ro[q2]]);
                    T[u * 8 + 4 + q2] = __ldg(&phi[ro[q2]]);
                }
            }
        };
        // combine + STS for part j of tile tt
        auto consume_part = [&](int tt, int j) {
            const uint32_t Aw = sb + SM_A + (tt & 1) * 16384 + mloc * 128;
#pragma unroll
            for (int u = 0; u < 2; u++) {
                int i = j * 2 + u;
                int ct = half * 16 + (i >> 2) * 8 + (i & 3);
                float vlo = rw[0] * T[u * 8 + 0] + rw[1] * T[u * 8 + 1]
                          + rw[2] * T[u * 8 + 2] + rw[3] * T[u * 8 + 3];
                float vhi = rw[0] * T[u * 8 + 4] + rw[1] * T[u * 8 + 5]
                          + rw[2] * T[u * 8 + 6] + rw[3] * T[u * 8 + 7];
                int cp = (ct & 0x18) | ((i & 3) << 1);
                uint32_t addr = Aw + ((((uint32_t)cp >> 2) ^ (mloc & 7)) << 4)
                              + ((cp & 3) << 2);
                asm volatile("st.shared.v2.b32 [%0], {%1,%2};"
                             :: "r"(addr),
                                "r"(__float_as_uint(to_tf32(vlo))),
                                "r"(__float_as_uint(to_tf32(vhi))) : "memory");
            }
        };
        // one ks sub-step of MMA(t)
        auto mma_ks = [&](uint32_t As, uint32_t Bs, int ks) {
            const int ch = ks * 2 + (tg >> 1);
            const int hb = (tg & 1) << 3;
            uint32_t a[4][4];
#pragma unroll
            for (int mt = 0; mt < 4; mt++) {
                int r1 = wm + mt * 16 + g;
                int r2 = r1 + 8;
                uint32_t ad1 = As + r1 * 128 + ((ch ^ (r1 & 7)) << 4) + hb;
                uint32_t ad2 = As + r2 * 128 + ((ch ^ (r2 & 7)) << 4) + hb;
                asm volatile("ld.shared.v2.b32 {%0,%1}, [%2];"
                             : "=r"(a[mt][0]), "=r"(a[mt][2]) : "r"(ad1));
                asm volatile("ld.shared.v2.b32 {%0,%1}, [%2];"
                             : "=r"(a[mt][1]), "=r"(a[mt][3]) : "r"(ad2));
            }
#pragma unroll
            for (int nt = 0; nt < 8; nt++) {
                int rr = wn + nt * 8 + g;
                uint32_t bd = Bs + rr * 128 + ((ch ^ (rr & 7)) << 4) + hb;
                uint32_t b[2];
                asm volatile("ld.shared.v2.b32 {%0,%1}, [%2];"
                             : "=r"(b[0]), "=r"(b[1]) : "r"(bd));
#pragma unroll
                for (int mt = 0; mt < 4; mt++)
                    MMA_TF32(c[mt][nt], a[mt], b);
            }
        };

        // prologue: full gather of tile 0
        compute_meta(0);
#pragma unroll
        for (int j = 0; j < 4; j++) { issue_part(0, j); consume_part(0, j); }

#pragma unroll 1
        for (int t = 0; t < NTILES; t++) {
            asm volatile("cp.async.wait_group 0;" ::: "memory");  // B(t) done
            __syncthreads();      // A(t) visible; B stage (t+1)&1 free

            if (t + 1 < NTILES) LOAD_B(t + 1);
            asm volatile("cp.async.commit_group;" ::: "memory");

            const uint32_t As = sb + SM_A + (t & 1) * 16384;
            const uint32_t Bs = sb + SM_B + (t & 1) * 32768;
            const bool nx = (t + 1 < NTILES);

            if (nx) {
                if (((t + 1) & 7) == 0) compute_meta((t + 1) >> 3);
                issue_part(t + 1, 0);        // LDGs in flight during ks=0
            }
            mma_ks(As, Bs, 0);
            if (nx) { consume_part(t + 1, 0); issue_part(t + 1, 1); }
            mma_ks(As, Bs, 1);
            if (nx) { consume_part(t + 1, 1); issue_part(t + 1, 2); }
            mma_ks(As, Bs, 2);
            if (nx) { consume_part(t + 1, 2); issue_part(t + 1, 3); }
            mma_ks(As, Bs, 3);
            if (nx) consume_part(t + 1, 3);
        }

        // ---- epilogue ----
        float* ob = out + (size_t)nimg * OC * 4096 + (m0 & 4095);
#pragma unroll
        for (int mt = 0; mt < 4; mt++) {
            int lm = wm + mt * 16 + g;
#pragma unroll
            for (int nt = 0; nt < 8; nt++) {
                int o = wn + nt * 8 + tg * 2;
                ob[(size_t)o * 4096 + lm]           = c[mt][nt][0];
                ob[(size_t)(o + 1) * 4096 + lm]     = c[mt][nt][1];
                ob[(size_t)o * 4096 + lm + 8]       = c[mt][nt][2];
                ob[(size_t)(o + 1) * 4096 + lm + 8] = c[mt][nt][3];
            }
        }
    }
}

// ---------------------------------------------------------------------------
extern "C" void kernel_launch(void* const* d_in, const int* in_sizes, int n_in,
                              void* d_out, int out_size)
{
    const float* x      = (const float*)d_in[0];
    const float* conv_w = (const float*)d_in[1];
    const float* conv_b = (const float*)d_in[2];
    const float* dcn_w  = (const float*)d_in[3];
    float* out = (float*)d_out;

    cudaFuncSetAttribute(dcn_kernel,
                         cudaFuncAttributeMaxDynamicSharedMemorySize, DCN_SMEM);

    permute_w_kernel<<<OC, 256>>>(dcn_w);
    permute_woff_kernel<<<32, 256>>>(conv_w);
    dcn_kernel<<<MDIM / 128, 256, DCN_SMEM>>>(x, conv_b, out);
}